// round 2
// baseline (speedup 1.0000x reference)
#include <cuda_runtime.h>
#include <cuda_bf16.h>

#define BB 8
#define SS 1024
#define HH 512
#define NHD 8
#define HDD 64

// Scratch for projected Q (pre-scaled), K, V in [B, NH, S, HD] layout.
__device__ float g_q[BB * NHD * SS * HDD];
__device__ float g_k[BB * NHD * SS * HDD];
__device__ float g_v[BB * NHD * SS * HDD];

// ---------------------------------------------------------------------------
// Fused QKV projection: C[m][n] = sum_k X[m][k] * W[n][k] + bias[n]
// M = B*S = 8192, N = 512, K = 512.  grid.z selects {Q, K, V}.
// 64x64 output tile per CTA, 16-wide K tiles, 256 threads, 4x4 per thread.
// ---------------------------------------------------------------------------
__global__ __launch_bounds__(256) void qkv_kernel(
    const float* __restrict__ x,
    const float* __restrict__ Wq, const float* __restrict__ bq,
    const float* __restrict__ Wk, const float* __restrict__ bk,
    const float* __restrict__ Wv, const float* __restrict__ bv)
{
    __shared__ float a_s[64][20];   // [row][k] pad->20 floats (16B aligned rows)
    __shared__ float b_s[64][20];

    const float* W;
    const float* bias;
    float* out;
    float scale;
    int z = blockIdx.z;
    if (z == 0)      { W = Wq; bias = bq; out = g_q; scale = 0.125f; }  // 1/sqrt(64)
    else if (z == 1) { W = Wk; bias = bk; out = g_k; scale = 1.0f; }
    else             { W = Wv; bias = bv; out = g_v; scale = 1.0f; }

    int m0 = blockIdx.x * 64;
    int n0 = blockIdx.y * 64;
    int tid = threadIdx.x;
    int tx = tid & 15;
    int ty = tid >> 4;

    float acc[4][4] = {};

    for (int k0 = 0; k0 < HH; k0 += 16) {
        // load A tile (X rows) and B tile (W rows), float4 per thread
        {
            int r = tid >> 2;
            int c = (tid & 3) * 4;
            *(float4*)&a_s[r][c] = *(const float4*)(x + (size_t)(m0 + r) * HH + k0 + c);
            *(float4*)&b_s[r][c] = *(const float4*)(W + (size_t)(n0 + r) * HH + k0 + c);
        }
        __syncthreads();

        #pragma unroll
        for (int kk = 0; kk < 16; kk += 4) {
            float4 ar[4], br[4];
            #pragma unroll
            for (int i = 0; i < 4; i++) ar[i] = *(float4*)&a_s[4 * ty + i][kk];
            #pragma unroll
            for (int j = 0; j < 4; j++) br[j] = *(float4*)&b_s[4 * tx + j][kk];
            #pragma unroll
            for (int i = 0; i < 4; i++) {
                #pragma unroll
                for (int j = 0; j < 4; j++) {
                    acc[i][j] += ar[i].x * br[j].x + ar[i].y * br[j].y +
                                 ar[i].z * br[j].z + ar[i].w * br[j].w;
                }
            }
        }
        __syncthreads();
    }

    // Write out in [B, NH, S, HD] layout, 4 consecutive d per thread (same head).
    #pragma unroll
    for (int i = 0; i < 4; i++) {
        int m = m0 + 4 * ty + i;
        int b = m >> 10;
        int s = m & (SS - 1);
        int n = n0 + 4 * tx;           // 4-aligned => all 4 cols in same head
        int h = n >> 6;
        int d = n & (HDD - 1);
        float4 v;
        v.x = (acc[i][0] + bias[n + 0]) * scale;
        v.y = (acc[i][1] + bias[n + 1]) * scale;
        v.z = (acc[i][2] + bias[n + 2]) * scale;
        v.w = (acc[i][3] + bias[n + 3]) * scale;
        *(float4*)(out + (((size_t)(b * NHD + h) * SS + s) * HDD + d)) = v;
    }
}

// ---------------------------------------------------------------------------
// Flash attention with additive bias (rel_2d_pos + mask).
// grid: (S/64 q-blocks, B*NH).  256 threads, 4x4 scores per thread.
// smem: q, k, v, p tiles each [64][68] floats.
// ---------------------------------------------------------------------------
#define PAD 68
#define ATTN_SMEM (4 * 64 * PAD * sizeof(float))

__global__ __launch_bounds__(256) void attn_kernel(
    const float* __restrict__ rel,
    const float* __restrict__ mask,
    float* __restrict__ out)
{
    extern __shared__ float sm[];
    float (*q_s)[PAD] = (float(*)[PAD])sm;
    float (*k_s)[PAD] = q_s + 64;
    float (*v_s)[PAD] = k_s + 64;
    float (*p_s)[PAD] = v_s + 64;

    int bh = blockIdx.y;
    int b = bh >> 3;           // / NH
    int h = bh & (NHD - 1);
    int qb = blockIdx.x * 64;
    int tid = threadIdx.x;
    int tx = tid & 15;
    int ty = tid >> 4;

    // Load Q block (pre-scaled) once.
    const float* qptr = g_q + ((size_t)bh * SS + qb) * HDD;
    for (int idx = tid; idx < 64 * 16; idx += 256) {
        int r = idx >> 4;
        int c = (idx & 15) * 4;
        *(float4*)&q_s[r][c] = *(const float4*)(qptr + r * HDD + c);
    }

    float m_i[4], l_i[4];
    float acc[4][4] = {};
    #pragma unroll
    for (int i = 0; i < 4; i++) { m_i[i] = -1e30f; l_i[i] = 0.0f; }

    for (int kb = 0; kb < SS; kb += 64) {
        __syncthreads();   // previous iteration fully done with k_s/v_s/p_s

        const float* kptr = g_k + ((size_t)bh * SS + kb) * HDD;
        const float* vptr = g_v + ((size_t)bh * SS + kb) * HDD;
        for (int idx = tid; idx < 64 * 16; idx += 256) {
            int r = idx >> 4;
            int c = (idx & 15) * 4;
            *(float4*)&k_s[r][c] = *(const float4*)(kptr + r * HDD + c);
            *(float4*)&v_s[r][c] = *(const float4*)(vptr + r * HDD + c);
        }
        __syncthreads();

        // Scores: s4[i][j] = q_row(4ty+i) . k_row(4tx+j)
        float s4[4][4] = {};
        #pragma unroll
        for (int kk = 0; kk < 64; kk += 4) {
            float4 qr[4], kr[4];
            #pragma unroll
            for (int i = 0; i < 4; i++) qr[i] = *(float4*)&q_s[4 * ty + i][kk];
            #pragma unroll
            for (int j = 0; j < 4; j++) kr[j] = *(float4*)&k_s[4 * tx + j][kk];
            #pragma unroll
            for (int i = 0; i < 4; i++) {
                #pragma unroll
                for (int j = 0; j < 4; j++) {
                    s4[i][j] += qr[i].x * kr[j].x + qr[i].y * kr[j].y +
                                qr[i].z * kr[j].z + qr[i].w * kr[j].w;
                }
            }
        }

        // Bias add: rel_2d_pos[b][h][qrow][kcol] + mask[b][kcol]
        {
            float4 mk = *(const float4*)(mask + b * SS + kb + 4 * tx);
            #pragma unroll
            for (int i = 0; i < 4; i++) {
                const float* rp = rel + (size_t)bh * SS * SS +
                                  (size_t)(qb + 4 * ty + i) * SS + kb + 4 * tx;
                float4 bi = *(const float4*)rp;
                s4[i][0] += bi.x + mk.x;
                s4[i][1] += bi.y + mk.y;
                s4[i][2] += bi.z + mk.z;
                s4[i][3] += bi.w + mk.w;
            }
        }

        // Online softmax per score row (16 threads with same ty share rows).
        #pragma unroll
        for (int i = 0; i < 4; i++) {
            float mx = fmaxf(fmaxf(s4[i][0], s4[i][1]), fmaxf(s4[i][2], s4[i][3]));
            #pragma unroll
            for (int off = 1; off < 16; off <<= 1)
                mx = fmaxf(mx, __shfl_xor_sync(0xffffffffu, mx, off));
            float mnew = fmaxf(m_i[i], mx);
            float corr = __expf(m_i[i] - mnew);
            m_i[i] = mnew;
            float rs = 0.0f;
            #pragma unroll
            for (int j = 0; j < 4; j++) {
                s4[i][j] = __expf(s4[i][j] - mnew);
                rs += s4[i][j];
            }
            #pragma unroll
            for (int off = 1; off < 16; off <<= 1)
                rs += __shfl_xor_sync(0xffffffffu, rs, off);
            l_i[i] = l_i[i] * corr + rs;
            #pragma unroll
            for (int j = 0; j < 4; j++) acc[i][j] *= corr;
        }

        // Stage probabilities for PV gemm.
        #pragma unroll
        for (int i = 0; i < 4; i++)
            *(float4*)&p_s[4 * ty + i][4 * tx] = make_float4(s4[i][0], s4[i][1], s4[i][2], s4[i][3]);
        __syncthreads();

        // acc[i][j] += sum_kk p_s[4ty+i][kk] * v_s[kk][4tx+j]
        #pragma unroll
        for (int kk = 0; kk < 64; kk += 4) {
            float pa[4][4];
            #pragma unroll
            for (int i = 0; i < 4; i++)
                *(float4*)&pa[i][0] = *(float4*)&p_s[4 * ty + i][kk];
            #pragma unroll
            for (int t = 0; t < 4; t++) {
                float4 vv = *(float4*)&v_s[kk + t][4 * tx];
                #pragma unroll
                for (int i = 0; i < 4; i++) {
                    acc[i][0] += pa[i][t] * vv.x;
                    acc[i][1] += pa[i][t] * vv.y;
                    acc[i][2] += pa[i][t] * vv.z;
                    acc[i][3] += pa[i][t] * vv.w;
                }
            }
        }
    }

    // Normalize and write out [B, S, H] with H = h*HD + d.
    #pragma unroll
    for (int i = 0; i < 4; i++) {
        float inv = 1.0f / l_i[i];
        int qrow = qb + 4 * ty + i;
        float4 v;
        v.x = acc[i][0] * inv;
        v.y = acc[i][1] * inv;
        v.z = acc[i][2] * inv;
        v.w = acc[i][3] * inv;
        *(float4*)(out + ((size_t)b * SS + qrow) * HH + h * HDD + 4 * tx) = v;
    }
}

extern "C" void kernel_launch(void* const* d_in, const int* in_sizes, int n_in,
                              void* d_out, int out_size)
{
    const float* x    = (const float*)d_in[0];
    const float* mask = (const float*)d_in[1];
    const float* rel  = (const float*)d_in[2];
    const float* Wq   = (const float*)d_in[3];
    const float* bq   = (const float*)d_in[4];
    const float* Wk   = (const float*)d_in[5];
    const float* bk   = (const float*)d_in[6];
    const float* Wv   = (const float*)d_in[7];
    const float* bv   = (const float*)d_in[8];
    float* out = (float*)d_out;

    qkv_kernel<<<dim3(BB * SS / 64, HH / 64, 3), 256>>>(x, Wq, bq, Wk, bk, Wv, bv);

    cudaFuncSetAttribute(attn_kernel, cudaFuncAttributeMaxDynamicSharedMemorySize,
                         (int)ATTN_SMEM);
    attn_kernel<<<dim3(SS / 64, BB * NHD), 256, ATTN_SMEM>>>(rel, mask, out);
}

// round 4
// speedup vs baseline: 7.2293x; 7.2293x over previous
#include <cuda_runtime.h>
#include <cuda_bf16.h>
#include <cstdint>

#define BB 8
#define SS 1024
#define HH 512
#define NHD 8
#define HDD 64

// Scratch for projected Q (pre-scaled), K, V in [B, NH, S, HD] layout.
__device__ float g_q[BB * NHD * SS * HDD];
__device__ float g_k[BB * NHD * SS * HDD];
__device__ float g_v[BB * NHD * SS * HDD];

// ---------------------------------------------------------------------------
// TF32 helpers
// ---------------------------------------------------------------------------
__device__ __forceinline__ float to_tf32(float x) {
    asm("cvt.rna.tf32.f32 %0, %0;" : "+f"(x));
    return x;
}

__device__ __forceinline__ void mma_tf32(float* c,
                                         uint32_t a0, uint32_t a1, uint32_t a2, uint32_t a3,
                                         uint32_t b0, uint32_t b1) {
    asm volatile(
        "mma.sync.aligned.m16n8k8.row.col.f32.tf32.tf32.f32 "
        "{%0,%1,%2,%3}, {%4,%5,%6,%7}, {%8,%9}, {%0,%1,%2,%3};"
        : "+f"(c[0]), "+f"(c[1]), "+f"(c[2]), "+f"(c[3])
        : "r"(a0), "r"(a1), "r"(a2), "r"(a3), "r"(b0), "r"(b1));
}

__device__ __forceinline__ uint32_t f2b(float x) { return __float_as_uint(x); }

// ---------------------------------------------------------------------------
// Fused QKV projection with tf32 mma:
//   C[m][n] = sum_k X[m][k] * W[n][k] + bias[n]    (M=8192, N=512, K=512)
// CTA: 64x64 tile, 4 warps (2x2 of 32x32 warp tiles), K-tile = 32.
// grid.z selects {Q, K, V}.
// ---------------------------------------------------------------------------
#define QKV_STR 36

__global__ __launch_bounds__(128) void qkv_kernel(
    const float* __restrict__ x,
    const float* __restrict__ Wq, const float* __restrict__ bq,
    const float* __restrict__ Wk, const float* __restrict__ bk,
    const float* __restrict__ Wv, const float* __restrict__ bv)
{
    __shared__ float a_s[64][QKV_STR];
    __shared__ float b_s[64][QKV_STR];

    const float* W;
    const float* bias;
    float* out;
    float scale;
    int z = blockIdx.z;
    if (z == 0)      { W = Wq; bias = bq; out = g_q; scale = 0.125f; }  // 1/sqrt(64)
    else if (z == 1) { W = Wk; bias = bk; out = g_k; scale = 1.0f; }
    else             { W = Wv; bias = bv; out = g_v; scale = 1.0f; }

    int m0 = blockIdx.x * 64;
    int n0 = blockIdx.y * 64;
    int tid = threadIdx.x;
    int wid = tid >> 5;
    int lane = tid & 31;
    int gi = lane >> 2;       // group id (0..7)
    int ti = lane & 3;        // thread in group (0..3)
    int wm = (wid >> 1) * 32; // warp m offset within CTA tile
    int wn = (wid & 1) * 32;  // warp n offset

    float acc[2][4][4] = {};

    for (int k0 = 0; k0 < HH; k0 += 32) {
        // Stage A (X rows) and B (W rows), tf32-converted. 64x32 each.
        // 128 threads * 4 float4 per array.
        #pragma unroll
        for (int it = 0; it < 4; it++) {
            int idx = tid + it * 128;          // 0..511 float4 slots
            int r = idx >> 3;
            int c = (idx & 7) * 4;
            float4 av = *(const float4*)(x + (size_t)(m0 + r) * HH + k0 + c);
            float4 bv = *(const float4*)(W + (size_t)(n0 + r) * HH + k0 + c);
            av.x = to_tf32(av.x); av.y = to_tf32(av.y);
            av.z = to_tf32(av.z); av.w = to_tf32(av.w);
            bv.x = to_tf32(bv.x); bv.y = to_tf32(bv.y);
            bv.z = to_tf32(bv.z); bv.w = to_tf32(bv.w);
            *(float4*)&a_s[r][c] = av;
            *(float4*)&b_s[r][c] = bv;
        }
        __syncthreads();

        #pragma unroll
        for (int kk = 0; kk < 32; kk += 8) {
            uint32_t a[2][4];
            #pragma unroll
            for (int mf = 0; mf < 2; mf++) {
                int r = wm + mf * 16 + gi;
                a[mf][0] = f2b(a_s[r][kk + ti]);
                a[mf][1] = f2b(a_s[r + 8][kk + ti]);
                a[mf][2] = f2b(a_s[r][kk + ti + 4]);
                a[mf][3] = f2b(a_s[r + 8][kk + ti + 4]);
            }
            #pragma unroll
            for (int nf = 0; nf < 4; nf++) {
                int rn = wn + nf * 8 + gi;
                uint32_t b0 = f2b(b_s[rn][kk + ti]);
                uint32_t b1 = f2b(b_s[rn][kk + ti + 4]);
                #pragma unroll
                for (int mf = 0; mf < 2; mf++)
                    mma_tf32(acc[mf][nf], a[mf][0], a[mf][1], a[mf][2], a[mf][3], b0, b1);
            }
        }
        __syncthreads();
    }

    // Epilogue: bias + scale, write [B, NH, S, HD].
    #pragma unroll
    for (int mf = 0; mf < 2; mf++) {
        #pragma unroll
        for (int nf = 0; nf < 4; nf++) {
            int n = n0 + wn + nf * 8 + ti * 2;     // 2-aligned, stays in one head
            int h = n >> 6;
            int d = n & (HDD - 1);
            float2 bv = *(const float2*)(bias + n);
            #pragma unroll
            for (int rr = 0; rr < 2; rr++) {
                int m = m0 + wm + mf * 16 + gi + rr * 8;
                int b = m >> 10;
                int s = m & (SS - 1);
                float2 ov;
                ov.x = (acc[mf][nf][rr * 2 + 0] + bv.x) * scale;
                ov.y = (acc[mf][nf][rr * 2 + 1] + bv.y) * scale;
                *(float2*)(out + (((size_t)(b * NHD + h) * SS + s) * HDD + d)) = ov;
            }
        }
    }
}

// ---------------------------------------------------------------------------
// Flash attention with tf32 mma + additive bias (rel_2d_pos + mask).
// CTA: 64 Q rows x 64-key tiles, 4 warps (16 Q rows each).
// grid: (S/64, B*NH), 128 threads.
// ---------------------------------------------------------------------------
#define ASTR 68
#define ATTN_SMEM (4 * 64 * ASTR * sizeof(float))

__global__ __launch_bounds__(128) void attn_kernel(
    const float* __restrict__ rel,
    const float* __restrict__ mask,
    float* __restrict__ out)
{
    extern __shared__ float sm[];
    float (*q_s)[ASTR] = (float(*)[ASTR])sm;
    float (*k_s)[ASTR] = q_s + 64;
    float (*v_s)[ASTR] = k_s + 64;
    float (*p_s)[ASTR] = v_s + 64;

    int bh = blockIdx.y;
    int b = bh >> 3;
    int h = bh & (NHD - 1);
    int qb = blockIdx.x * 64;
    int tid = threadIdx.x;
    int wid = tid >> 5;
    int lane = tid & 31;
    int gi = lane >> 2;
    int ti = lane & 3;
    int mrow = wid * 16;                 // warp's Q-row offset within block

    // Load Q block once (already pre-scaled by 1/sqrt(HD)), tf32-converted.
    const float* qptr = g_q + ((size_t)bh * SS + qb) * HDD;
    #pragma unroll
    for (int it = 0; it < 8; it++) {
        int idx = tid + it * 128;        // 0..1023 float4 slots
        int r = idx >> 4;
        int c = (idx & 15) * 4;
        float4 t = *(const float4*)(qptr + r * HDD + c);
        t.x = to_tf32(t.x); t.y = to_tf32(t.y);
        t.z = to_tf32(t.z); t.w = to_tf32(t.w);
        *(float4*)&q_s[r][c] = t;
    }

    float m_i[2] = {-1e30f, -1e30f};
    float l_i[2] = {0.0f, 0.0f};
    float o[8][4] = {};

    const float* rel_base = rel + (size_t)bh * SS * SS + (size_t)(qb + mrow + gi) * SS;
    const float* mask_base = mask + b * SS;

    for (int kb = 0; kb < SS; kb += 64) {
        __syncthreads();                 // previous tile fully consumed

        // Stage K and V tiles (64x64 each), tf32-converted.
        const float* kp = g_k + ((size_t)bh * SS + kb) * HDD;
        const float* vp = g_v + ((size_t)bh * SS + kb) * HDD;
        #pragma unroll
        for (int it = 0; it < 8; it++) {
            int idx = tid + it * 128;
            int r = idx >> 4;
            int c = (idx & 15) * 4;
            float4 kv = *(const float4*)(kp + r * HDD + c);
            float4 vv = *(const float4*)(vp + r * HDD + c);
            kv.x = to_tf32(kv.x); kv.y = to_tf32(kv.y);
            kv.z = to_tf32(kv.z); kv.w = to_tf32(kv.w);
            vv.x = to_tf32(vv.x); vv.y = to_tf32(vv.y);
            vv.z = to_tf32(vv.z); vv.w = to_tf32(vv.w);
            *(float4*)&k_s[r][c] = kv;
            *(float4*)&v_s[r][c] = vv;
        }
        __syncthreads();

        // ---- S = Q K^T : per warp 16x64, 8 n-frags, k over 64 in steps of 8.
        float s[8][4] = {};
        #pragma unroll
        for (int kk = 0; kk < 64; kk += 8) {
            uint32_t a0 = f2b(q_s[mrow + gi][kk + ti]);
            uint32_t a1 = f2b(q_s[mrow + gi + 8][kk + ti]);
            uint32_t a2 = f2b(q_s[mrow + gi][kk + ti + 4]);
            uint32_t a3 = f2b(q_s[mrow + gi + 8][kk + ti + 4]);
            #pragma unroll
            for (int nf = 0; nf < 8; nf++) {
                uint32_t b0 = f2b(k_s[nf * 8 + gi][kk + ti]);
                uint32_t b1 = f2b(k_s[nf * 8 + gi][kk + ti + 4]);
                mma_tf32(s[nf], a0, a1, a2, a3, b0, b1);
            }
        }

        // ---- bias: rel_2d_pos[b][h][qrow][kcol] + mask[b][kcol]
        #pragma unroll
        for (int nf = 0; nf < 8; nf++) {
            int col = kb + nf * 8 + ti * 2;
            float2 bi0 = *(const float2*)(rel_base + col);
            float2 bi1 = *(const float2*)(rel_base + 8 * SS + col);
            float2 mk  = *(const float2*)(mask_base + col);
            s[nf][0] += bi0.x + mk.x;
            s[nf][1] += bi0.y + mk.y;
            s[nf][2] += bi1.x + mk.x;
            s[nf][3] += bi1.y + mk.y;
        }

        // ---- online softmax: two rows per thread (gi, gi+8 within warp tile)
        float mx0 = -1e30f, mx1 = -1e30f;
        #pragma unroll
        for (int nf = 0; nf < 8; nf++) {
            mx0 = fmaxf(mx0, fmaxf(s[nf][0], s[nf][1]));
            mx1 = fmaxf(mx1, fmaxf(s[nf][2], s[nf][3]));
        }
        #pragma unroll
        for (int off = 1; off < 4; off <<= 1) {
            mx0 = fmaxf(mx0, __shfl_xor_sync(0xffffffffu, mx0, off));
            mx1 = fmaxf(mx1, __shfl_xor_sync(0xffffffffu, mx1, off));
        }
        float mn0 = fmaxf(m_i[0], mx0);
        float mn1 = fmaxf(m_i[1], mx1);
        float corr0 = __expf(m_i[0] - mn0);
        float corr1 = __expf(m_i[1] - mn1);
        m_i[0] = mn0; m_i[1] = mn1;

        float rs0 = 0.0f, rs1 = 0.0f;
        #pragma unroll
        for (int nf = 0; nf < 8; nf++) {
            s[nf][0] = __expf(s[nf][0] - mn0);
            s[nf][1] = __expf(s[nf][1] - mn0);
            s[nf][2] = __expf(s[nf][2] - mn1);
            s[nf][3] = __expf(s[nf][3] - mn1);
            rs0 += s[nf][0] + s[nf][1];
            rs1 += s[nf][2] + s[nf][3];
        }
        #pragma unroll
        for (int off = 1; off < 4; off <<= 1) {
            rs0 += __shfl_xor_sync(0xffffffffu, rs0, off);
            rs1 += __shfl_xor_sync(0xffffffffu, rs1, off);
        }
        l_i[0] = l_i[0] * corr0 + rs0;
        l_i[1] = l_i[1] * corr1 + rs1;
        #pragma unroll
        for (int nf = 0; nf < 8; nf++) {
            o[nf][0] *= corr0; o[nf][1] *= corr0;
            o[nf][2] *= corr1; o[nf][3] *= corr1;
        }

        // ---- stage P (tf32) for PV; each warp writes only its own 16 rows.
        #pragma unroll
        for (int nf = 0; nf < 8; nf++) {
            float2 p0 = make_float2(to_tf32(s[nf][0]), to_tf32(s[nf][1]));
            float2 p1 = make_float2(to_tf32(s[nf][2]), to_tf32(s[nf][3]));
            *(float2*)&p_s[mrow + gi][nf * 8 + ti * 2]     = p0;
            *(float2*)&p_s[mrow + gi + 8][nf * 8 + ti * 2] = p1;
        }
        __syncwarp();

        // ---- O += P V : A = P (16 x 64 keys), B = V[key][d]
        #pragma unroll
        for (int kk = 0; kk < 64; kk += 8) {
            uint32_t a0 = f2b(p_s[mrow + gi][kk + ti]);
            uint32_t a1 = f2b(p_s[mrow + gi + 8][kk + ti]);
            uint32_t a2 = f2b(p_s[mrow + gi][kk + ti + 4]);
            uint32_t a3 = f2b(p_s[mrow + gi + 8][kk + ti + 4]);
            #pragma unroll
            for (int nf = 0; nf < 8; nf++) {
                uint32_t b0 = f2b(v_s[kk + ti][nf * 8 + gi]);
                uint32_t b1 = f2b(v_s[kk + ti + 4][nf * 8 + gi]);
                mma_tf32(o[nf], a0, a1, a2, a3, b0, b1);
            }
        }
    }

    // ---- normalize + write out [B, S, H], H index = h*64 + d.
    float inv0 = 1.0f / l_i[0];
    float inv1 = 1.0f / l_i[1];
    int qr0 = qb + mrow + gi;
    #pragma unroll
    for (int nf = 0; nf < 8; nf++) {
        int d = nf * 8 + ti * 2;
        float2 o0 = make_float2(o[nf][0] * inv0, o[nf][1] * inv0);
        float2 o1 = make_float2(o[nf][2] * inv1, o[nf][3] * inv1);
        *(float2*)(out + ((size_t)b * SS + qr0) * HH + h * HDD + d)       = o0;
        *(float2*)(out + ((size_t)b * SS + qr0 + 8) * HH + h * HDD + d)   = o1;
    }
}

extern "C" void kernel_launch(void* const* d_in, const int* in_sizes, int n_in,
                              void* d_out, int out_size)
{
    const float* x    = (const float*)d_in[0];
    const float* mask = (const float*)d_in[1];
    const float* rel  = (const float*)d_in[2];
    const float* Wq   = (const float*)d_in[3];
    const float* bq   = (const float*)d_in[4];
    const float* Wk   = (const float*)d_in[5];
    const float* bk   = (const float*)d_in[6];
    const float* Wv   = (const float*)d_in[7];
    const float* bv   = (const float*)d_in[8];
    float* out = (float*)d_out;

    qkv_kernel<<<dim3(BB * SS / 64, HH / 64, 3), 128>>>(x, Wq, bq, Wk, bk, Wv, bv);

    cudaFuncSetAttribute(attn_kernel, cudaFuncAttributeMaxDynamicSharedMemorySize,
                         (int)ATTN_SMEM);
    attn_kernel<<<dim3(SS / 64, BB * NHD), 128, ATTN_SMEM>>>(rel, mask, out);
}

// round 9
// speedup vs baseline: 7.3045x; 1.0104x over previous
#include <cuda_runtime.h>
#include <cuda_bf16.h>
#include <cstdint>

#define BB 8
#define SS 1024
#define HH 512
#define NHD 8
#define HDD 64

// Scratch: Q (pre-scaled), K in [B,NH,S,HD]; V TRANSPOSED in [B,NH,HD,S].
__device__ float g_q[BB * NHD * SS * HDD];
__device__ float g_k[BB * NHD * SS * HDD];
__device__ float g_v[BB * NHD * SS * HDD];

// ---------------------------------------------------------------------------
// helpers
// ---------------------------------------------------------------------------
__device__ __forceinline__ float to_tf32(float x) {
    asm("cvt.rna.tf32.f32 %0, %0;" : "+f"(x));
    return x;
}
__device__ __forceinline__ void mma_tf32(float* c,
                                         uint32_t a0, uint32_t a1, uint32_t a2, uint32_t a3,
                                         uint32_t b0, uint32_t b1) {
    asm volatile(
        "mma.sync.aligned.m16n8k8.row.col.f32.tf32.tf32.f32 "
        "{%0,%1,%2,%3}, {%4,%5,%6,%7}, {%8,%9}, {%0,%1,%2,%3};"
        : "+f"(c[0]), "+f"(c[1]), "+f"(c[2]), "+f"(c[3])
        : "r"(a0), "r"(a1), "r"(a2), "r"(a3), "r"(b0), "r"(b1));
}
__device__ __forceinline__ void ldsm_x4(uint32_t& r0, uint32_t& r1,
                                        uint32_t& r2, uint32_t& r3, uint32_t addr) {
    asm volatile("ldmatrix.sync.aligned.m8n8.x4.shared.b16 {%0,%1,%2,%3}, [%4];"
                 : "=r"(r0), "=r"(r1), "=r"(r2), "=r"(r3) : "r"(addr));
}
__device__ __forceinline__ uint32_t s2u(const void* p) {
    return (uint32_t)__cvta_generic_to_shared(p);
}

#define L2E 1.4426950408889634f

// ---------------------------------------------------------------------------
// Fused QKV projection (tf32 mma + ldmatrix):
//   C[m][n] = sum_k X[m][k] * W[n][k] + bias[n]   (M=8192, N=512, K=512)
// CTA: 64x64 tile, 4 warps (2x2 of 32x32), K-tile 32. grid.z = {Q,K,V}.
// V is written TRANSPOSED ([bh][d][s]).
// ---------------------------------------------------------------------------
#define QKV_STR 36

__global__ __launch_bounds__(128) void qkv_kernel(
    const float* __restrict__ x,
    const float* __restrict__ Wq, const float* __restrict__ bq,
    const float* __restrict__ Wk, const float* __restrict__ bk,
    const float* __restrict__ Wv, const float* __restrict__ bv)
{
    __shared__ float a_s[64][QKV_STR];
    __shared__ float b_s[64][QKV_STR];

    const float* W;
    const float* bias;
    float* out;
    float scale;
    int z = blockIdx.z;
    if (z == 0)      { W = Wq; bias = bq; out = g_q; scale = 0.125f; }
    else if (z == 1) { W = Wk; bias = bk; out = g_k; scale = 1.0f; }
    else             { W = Wv; bias = bv; out = g_v; scale = 1.0f; }

    int m0 = blockIdx.x * 64;
    int n0 = blockIdx.y * 64;
    int tid = threadIdx.x;
    int wid = tid >> 5;
    int lane = tid & 31;
    int gi = lane >> 2;
    int ti = lane & 3;
    int wm = (wid >> 1) * 32;
    int wn = (wid & 1) * 32;
    int lr = lane & 7;
    int mi = lane >> 3;

    // ldmatrix per-lane base addresses (bytes)
    uint32_t aA[2], bB[2];
    #pragma unroll
    for (int mf = 0; mf < 2; mf++)
        aA[mf] = s2u(&a_s[wm + mf * 16 + (mi & 1) * 8 + lr][(mi >> 1) * 4]);
    #pragma unroll
    for (int nfp = 0; nfp < 2; nfp++)
        bB[nfp] = s2u(&b_s[wn + nfp * 16 + (mi >> 1) * 8 + lr][(mi & 1) * 4]);

    float acc[2][4][4] = {};

    for (int k0 = 0; k0 < HH; k0 += 32) {
        // Prefetch next tile into registers BEFORE the barrier: LDG latency
        // overlaps the previous iteration's compute tail + barrier wait.
        float4 areg[4], breg[4];
        #pragma unroll
        for (int it = 0; it < 4; it++) {
            int idx = tid + it * 128;
            int r = idx >> 3;
            int c = (idx & 7) * 4;
            areg[it] = *(const float4*)(x + (size_t)(m0 + r) * HH + k0 + c);
            breg[it] = *(const float4*)(W + (size_t)(n0 + r) * HH + k0 + c);
        }
        __syncthreads();
        #pragma unroll
        for (int it = 0; it < 4; it++) {
            int idx = tid + it * 128;
            int r = idx >> 3;
            int c = (idx & 7) * 4;
            float4 av = areg[it], bv2 = breg[it];
            av.x = to_tf32(av.x); av.y = to_tf32(av.y);
            av.z = to_tf32(av.z); av.w = to_tf32(av.w);
            bv2.x = to_tf32(bv2.x); bv2.y = to_tf32(bv2.y);
            bv2.z = to_tf32(bv2.z); bv2.w = to_tf32(bv2.w);
            *(float4*)&a_s[r][c] = av;
            *(float4*)&b_s[r][c] = bv2;
        }
        __syncthreads();

        #pragma unroll
        for (int kk = 0; kk < 32; kk += 8) {
            uint32_t a[2][4];
            #pragma unroll
            for (int mf = 0; mf < 2; mf++)
                ldsm_x4(a[mf][0], a[mf][1], a[mf][2], a[mf][3], aA[mf] + kk * 4);
            #pragma unroll
            for (int nfp = 0; nfp < 2; nfp++) {
                uint32_t r0, r1, r2, r3;
                ldsm_x4(r0, r1, r2, r3, bB[nfp] + kk * 4);
                #pragma unroll
                for (int mf = 0; mf < 2; mf++) {
                    mma_tf32(acc[mf][2 * nfp + 0], a[mf][0], a[mf][1], a[mf][2], a[mf][3], r0, r1);
                    mma_tf32(acc[mf][2 * nfp + 1], a[mf][0], a[mf][1], a[mf][2], a[mf][3], r2, r3);
                }
            }
        }
        __syncthreads();
    }

    // Epilogue
    #pragma unroll
    for (int mf = 0; mf < 2; mf++) {
        #pragma unroll
        for (int nf = 0; nf < 4; nf++) {
            int n = n0 + wn + nf * 8 + ti * 2;
            int h = n >> 6;
            int d = n & (HDD - 1);
            float2 bv2 = *(const float2*)(bias + n);
            #pragma unroll
            for (int rr = 0; rr < 2; rr++) {
                int m = m0 + wm + mf * 16 + gi + rr * 8;
                int b = m >> 10;
                int s = m & (SS - 1);
                float vx = (acc[mf][nf][rr * 2 + 0] + bv2.x) * scale;
                float vy = (acc[mf][nf][rr * 2 + 1] + bv2.y) * scale;
                if (z == 2) {
                    // transposed: [bh][d][s]
                    size_t base = ((size_t)(b * NHD + h) * HDD);
                    out[(base + d)     * SS + s] = vx;
                    out[(base + d + 1) * SS + s] = vy;
                } else {
                    *(float2*)(out + (((size_t)(b * NHD + h) * SS + s) * HDD + d)) =
                        make_float2(vx, vy);
                }
            }
        }
    }
}

// ---------------------------------------------------------------------------
// Flash attention, tf32 mma + ldmatrix fragment loads.
// CTA: 256 threads (8 warps x 16 Q rows = 128-row Q block), 64-key tiles.
// grid: (S/128, B*NH) = (8, 64).
// ---------------------------------------------------------------------------
#define ASTR 68
#define ATTN_SMEM ((128 + 64 + 64 + 128) * ASTR * sizeof(float))

__global__ __launch_bounds__(256, 2) void attn_kernel(
    const float* __restrict__ rel,
    const float* __restrict__ mask,
    float* __restrict__ out)
{
    extern __shared__ float sm[];
    float (*q_s)[ASTR] = (float(*)[ASTR])sm;   // [128][.] Q rows
    float (*k_s)[ASTR] = q_s + 128;            // [64][.]  K rows (key-major)
    float (*v_s)[ASTR] = k_s + 64;             // [64][.]  V^T rows (d-major)
    float (*p_s)[ASTR] = v_s + 64;             // [128][.] P rows

    int bh = blockIdx.y;
    int b = bh >> 3;
    int h = bh & (NHD - 1);
    int qb = blockIdx.x * 128;
    int tid = threadIdx.x;
    int wid = tid >> 5;
    int lane = tid & 31;
    int gi = lane >> 2;
    int ti = lane & 3;
    int mrow = wid * 16;
    int lr = lane & 7;
    int mi = lane >> 3;

    // Stage Q (128 x 64), tf32-converted.
    const float* qptr = g_q + ((size_t)bh * SS + qb) * HDD;
    #pragma unroll
    for (int it = 0; it < 8; it++) {
        int idx = tid + it * 256;
        int r = idx >> 4;
        int c = (idx & 15) * 4;
        float4 t = *(const float4*)(qptr + r * HDD + c);
        t.x = to_tf32(t.x); t.y = to_tf32(t.y);
        t.z = to_tf32(t.z); t.w = to_tf32(t.w);
        *(float4*)&q_s[r][c] = t;
    }

    // ldmatrix per-lane base addresses.
    uint32_t qA = s2u(&q_s[mrow + (mi & 1) * 8 + lr][(mi >> 1) * 4]);
    uint32_t pA = s2u(&p_s[mrow + (mi & 1) * 8 + lr][(mi >> 1) * 4]);
    uint32_t kB = s2u(&k_s[(mi >> 1) * 8 + lr][(mi & 1) * 4]);
    uint32_t vB = s2u(&v_s[(mi >> 1) * 8 + lr][(mi & 1) * 4]);

    float m_i[2] = {-1e30f, -1e30f};
    float l_i[2] = {0.0f, 0.0f};
    float o[8][4] = {};

    const float* rel_base = rel + (size_t)bh * SS * SS + (size_t)(qb + mrow + gi) * SS;
    const float* mask_base = mask + b * SS;

    for (int kb = 0; kb < SS; kb += 64) {
        // Prefetch K / V^T tile into registers before the barrier.
        const float* kp = g_k + ((size_t)bh * SS + kb) * HDD;   // [key][d]
        const float* vp = g_v + (size_t)bh * SS * HDD + kb;     // [d][s], col kb
        float4 kreg[4], vreg[4];
        #pragma unroll
        for (int it = 0; it < 4; it++) {
            int idx = tid + it * 256;
            int r = idx >> 4;
            int c = (idx & 15) * 4;
            kreg[it] = *(const float4*)(kp + r * HDD + c);
            vreg[it] = *(const float4*)(vp + (size_t)r * SS + c);
        }
        __syncthreads();
        #pragma unroll
        for (int it = 0; it < 4; it++) {
            int idx = tid + it * 256;
            int r = idx >> 4;
            int c = (idx & 15) * 4;
            float4 kv = kreg[it], vv = vreg[it];
            kv.x = to_tf32(kv.x); kv.y = to_tf32(kv.y);
            kv.z = to_tf32(kv.z); kv.w = to_tf32(kv.w);
            vv.x = to_tf32(vv.x); vv.y = to_tf32(vv.y);
            vv.z = to_tf32(vv.z); vv.w = to_tf32(vv.w);
            *(float4*)&k_s[r][c] = kv;
            *(float4*)&v_s[r][c] = vv;
        }
        __syncthreads();

        // ---- S = Q K^T (warp: 16 x 64)
        float s[8][4] = {};
        #pragma unroll
        for (int kk = 0; kk < 64; kk += 8) {
            uint32_t a0, a1, a2, a3;
            ldsm_x4(a0, a1, a2, a3, qA + kk * 4);
            #pragma unroll
            for (int nfp = 0; nfp < 4; nfp++) {
                uint32_t r0, r1, r2, r3;
                ldsm_x4(r0, r1, r2, r3, kB + (nfp * 16 * ASTR + kk) * 4);
                mma_tf32(s[2 * nfp + 0], a0, a1, a2, a3, r0, r1);
                mma_tf32(s[2 * nfp + 1], a0, a1, a2, a3, r2, r3);
            }
        }

        // ---- bias: rel_2d_pos[b][h][qrow][kcol] + mask[b][kcol]
        #pragma unroll
        for (int nf = 0; nf < 8; nf++) {
            int col = kb + nf * 8 + ti * 2;
            float2 bi0 = *(const float2*)(rel_base + col);
            float2 bi1 = *(const float2*)(rel_base + 8 * SS + col);
            float2 mk  = *(const float2*)(mask_base + col);
            s[nf][0] += bi0.x + mk.x;
            s[nf][1] += bi0.y + mk.y;
            s[nf][2] += bi1.x + mk.x;
            s[nf][3] += bi1.y + mk.y;
        }

        // ---- online softmax (rows gi, gi+8 of warp tile)
        float mx0 = -1e30f, mx1 = -1e30f;
        #pragma unroll
        for (int nf = 0; nf < 8; nf++) {
            mx0 = fmaxf(mx0, fmaxf(s[nf][0], s[nf][1]));
            mx1 = fmaxf(mx1, fmaxf(s[nf][2], s[nf][3]));
        }
        #pragma unroll
        for (int off = 1; off < 4; off <<= 1) {
            mx0 = fmaxf(mx0, __shfl_xor_sync(0xffffffffu, mx0, off));
            mx1 = fmaxf(mx1, __shfl_xor_sync(0xffffffffu, mx1, off));
        }
        float mn0 = fmaxf(m_i[0], mx0);
        float mn1 = fmaxf(m_i[1], mx1);
        float nm0 = -mn0 * L2E;
        float nm1 = -mn1 * L2E;
        float corr0 = exp2f(fmaf(m_i[0], L2E, nm0));
        float corr1 = exp2f(fmaf(m_i[1], L2E, nm1));
        m_i[0] = mn0; m_i[1] = mn1;

        float rs0 = 0.0f, rs1 = 0.0f;
        #pragma unroll
        for (int nf = 0; nf < 8; nf++) {
            s[nf][0] = exp2f(fmaf(s[nf][0], L2E, nm0));
            s[nf][1] = exp2f(fmaf(s[nf][1], L2E, nm0));
            s[nf][2] = exp2f(fmaf(s[nf][2], L2E, nm1));
            s[nf][3] = exp2f(fmaf(s[nf][3], L2E, nm1));
            rs0 += s[nf][0] + s[nf][1];
            rs1 += s[nf][2] + s[nf][3];
        }
        #pragma unroll
        for (int off = 1; off < 4; off <<= 1) {
            rs0 += __shfl_xor_sync(0xffffffffu, rs0, off);
            rs1 += __shfl_xor_sync(0xffffffffu, rs1, off);
        }
        l_i[0] = l_i[0] * corr0 + rs0;
        l_i[1] = l_i[1] * corr1 + rs1;
        #pragma unroll
        for (int nf = 0; nf < 8; nf++) {
            o[nf][0] *= corr0; o[nf][1] *= corr0;
            o[nf][2] *= corr1; o[nf][3] *= corr1;
        }

        // ---- stage P (tf32), warp-private rows.
        #pragma unroll
        for (int nf = 0; nf < 8; nf++) {
            float2 p0 = make_float2(to_tf32(s[nf][0]), to_tf32(s[nf][1]));
            float2 p1 = make_float2(to_tf32(s[nf][2]), to_tf32(s[nf][3]));
            *(float2*)&p_s[mrow + gi][nf * 8 + ti * 2]     = p0;
            *(float2*)&p_s[mrow + gi + 8][nf * 8 + ti * 2] = p1;
        }
        __syncwarp();

        // ---- O += P V (B frags from V^T, same addressing as K)
        #pragma unroll
        for (int kk = 0; kk < 64; kk += 8) {
            uint32_t a0, a1, a2, a3;
            ldsm_x4(a0, a1, a2, a3, pA + kk * 4);
            #pragma unroll
            for (int nfp = 0; nfp < 4; nfp++) {
                uint32_t r0, r1, r2, r3;
                ldsm_x4(r0, r1, r2, r3, vB + (nfp * 16 * ASTR + kk) * 4);
                mma_tf32(o[2 * nfp + 0], a0, a1, a2, a3, r0, r1);
                mma_tf32(o[2 * nfp + 1], a0, a1, a2, a3, r2, r3);
            }
        }
    }

    // ---- normalize + write [B, S, H]
    float inv0 = 1.0f / l_i[0];
    float inv1 = 1.0f / l_i[1];
    int qr0 = qb + mrow + gi;
    #pragma unroll
    for (int nf = 0; nf < 8; nf++) {
        int d = nf * 8 + ti * 2;
        float2 o0 = make_float2(o[nf][0] * inv0, o[nf][1] * inv0);
        float2 o1 = make_float2(o[nf][2] * inv1, o[nf][3] * inv1);
        *(float2*)(out + ((size_t)b * SS + qr0) * HH + h * HDD + d)     = o0;
        *(float2*)(out + ((size_t)b * SS + qr0 + 8) * HH + h * HDD + d) = o1;
    }
}

extern "C" void kernel_launch(void* const* d_in, const int* in_sizes, int n_in,
                              void* d_out, int out_size)
{
    const float* x    = (const float*)d_in[0];
    const float* mask = (const float*)d_in[1];
    const float* rel  = (const float*)d_in[2];
    const float* Wq   = (const float*)d_in[3];
    const float* bq   = (const float*)d_in[4];
    const float* Wk   = (const float*)d_in[5];
    const float* bk   = (const float*)d_in[6];
    const float* Wv   = (const float*)d_in[7];
    const float* bv   = (const float*)d_in[8];
    float* out = (float*)d_out;

    qkv_kernel<<<dim3(BB * SS / 64, HH / 64, 3), 128>>>(x, Wq, bq, Wk, bk, Wv, bv);

    cudaFuncSetAttribute(attn_kernel, cudaFuncAttributeMaxDynamicSharedMemorySize,
                         (int)ATTN_SMEM);
    attn_kernel<<<dim3(SS / 128, BB * NHD), 256, ATTN_SMEM>>>(rel, mask, out);
}